// round 11
// baseline (speedup 1.0000x reference)
#include <cuda_runtime.h>
#include <cuda_bf16.h>
#include <cstdint>

// Fused LSTM (Keras gates i,f,g,o; relu cell activation) + dense(10) + softmax.
// B=16384, T=28, F=28, H=128. One block owns RTILE=16 batch rows across all
// timesteps (recurrence is block-local; no inter-block sync).
//
// Design (frozen for first measurement):
//  * fma.rn.f32x2 (FFMA2) packed over adjacent UNIT pairs -> weight pairs are
//    contiguous in the ORIGINAL W/U layout, loaded as coalesced LDG.64.
//  * h and x live in shared duplicated as (v,v) float2 so one broadcast
//    LDS.64 feeds the packed multiplier (conflict-free, N=1 broadcast).
//  * h/x double-buffered -> exactly ONE __syncthreads per timestep.
//    Race audit: step t reads buf[t&1], writes buf[(t&1)^1]; all reads of a
//    buffer complete before the barrier, writes to it only occur after.
//  * next-step x prefetched into registers at the top of the step; the
//    ~160-iteration FFMA2 body hides its L2/DRAM latency.
//
// Model: 36.6 GMAC fp32 -> FFMA2 floor ~1.0 ms @ rt2; L2 weight re-stream
// ~7.3 GB (~0.6 ms) hidden under compute if L1 catches the 4x cross-group
// U reuse. Predicted 0.98-1.22 ms.

#define HCELLS 128
#define G4     512      // 4*H
#define RTILE  16       // batch rows per block
#define RTP    17       // padded row count for smem tiles
#define RP     4        // rows per thread (4 groups of 64 threads)
#define NKP    64       // unit-pairs (2 units per thread)
#define TSTEPS 28
#define FDIM   28
#define NCLS   10
#define XTOT   (RTILE * FDIM)   // 448 staged x values per step

typedef unsigned long long ull;

__device__ __forceinline__ float sigm(float z) { return 1.0f / (1.0f + __expf(-z)); }

__device__ __forceinline__ void ffma2(ull& acc, ull a, ull b) {
    asm("fma.rn.f32x2 %0, %1, %2, %0;" : "+l"(acc) : "l"(a), "l"(b));
}
__device__ __forceinline__ float lo32(ull v) { return __uint_as_float((unsigned)(v & 0xFFFFFFFFull)); }
__device__ __forceinline__ float hi32(ull v) { return __uint_as_float((unsigned)(v >> 32)); }

__global__ __launch_bounds__(256, 2)
void lstm_fused(const float* __restrict__ x, const float* __restrict__ W,
                const float* __restrict__ U, const float* __restrict__ b,
                const float* __restrict__ Wd, const float* __restrict__ bd,
                float* __restrict__ out)
{
    __shared__ float2 hsh[2][HCELLS][RTP];  // [buf][unit][row] = (h,h) duplicated
    __shared__ float2 xsh[2][FDIM][RTP];    // [buf][feat][row] = (x,x) duplicated

    const int tid   = threadIdx.x;
    const int kp    = tid & (NKP - 1);    // unit-pair id: owns units 2kp, 2kp+1
    const int grp   = tid >> 6;           // row group 0..3
    const int rbase = grp * RP;
    const long row0 = (long)blockIdx.x * RTILE;

    // x staging indices for this thread (2 elements covers 448 with 256 threads)
    const int i0 = tid;                  // < 448 always
    const int i1 = tid + 256;            // < 448 iff tid < 192
    const int r0 = i0 / FDIM, f0 = i0 % FDIM;
    const int r1 = i1 / FDIM, f1 = i1 % FDIM;
    const float* xrow0 = x + (row0 + r0) * (TSTEPS * FDIM) + f0;
    const float* xrow1 = (i1 < XTOT) ? x + (row0 + r1) * (TSTEPS * FDIM) + f1 : nullptr;

    // init h(buf 0) = 0
    for (int i = tid; i < HCELLS * RTP; i += 256)
        (&hsh[0][0][0])[i] = make_float2(0.0f, 0.0f);
    // preload x[:, t=0, :] into buf 0, duplicated
    {
        float v0 = xrow0[0];
        xsh[0][f0][r0] = make_float2(v0, v0);
        if (xrow1) { float v1 = xrow1[0]; xsh[0][f1][r1] = make_float2(v1, v1); }
    }

    float c[RP][2];
    #pragma unroll
    for (int r = 0; r < RP; r++) { c[r][0] = 0.0f; c[r][1] = 0.0f; }

    // bias pairs (contiguous, 8B-aligned since 2kp is even)
    ull bz[4];
    #pragma unroll
    for (int g = 0; g < 4; g++)
        bz[g] = *(const ull*)&b[g * HCELLS + 2 * kp];

    const float* Wp = W + 2 * kp;   // W: [FDIM][G4] row-major
    const float* Up = U + 2 * kp;   // U: [HCELLS][G4] row-major

    __syncthreads();

    for (int t = 0; t < TSTEPS; t++) {
        const int cur = t & 1;
        const int nxt = cur ^ 1;

        // prefetch next-step x into registers FIRST; the whole W+U compute
        // below hides its latency
        float xp0 = 0.0f, xp1 = 0.0f;
        if (t < TSTEPS - 1) {
            xp0 = xrow0[(t + 1) * FDIM];
            if (xrow1) xp1 = xrow1[(t + 1) * FDIM];
        }

        ull ai[RP], af[RP], ag[RP], ao[RP];
        #pragma unroll
        for (int r = 0; r < RP; r++) { ai[r] = bz[0]; af[r] = bz[1]; ag[r] = bz[2]; ao[r] = bz[3]; }

        // z += x_t @ W  (F=28 inner dim)
        #pragma unroll 4
        for (int f = 0; f < FDIM; f++) {
            const ull w0 = *(const ull*)&Wp[f * G4];
            const ull w1 = *(const ull*)&Wp[f * G4 + 128];
            const ull w2 = *(const ull*)&Wp[f * G4 + 256];
            const ull w3 = *(const ull*)&Wp[f * G4 + 384];
            #pragma unroll
            for (int r = 0; r < RP; r++) {
                const ull xv = *(const ull*)&xsh[cur][f][rbase + r];  // broadcast LDS.64
                ffma2(ai[r], xv, w0);
                ffma2(af[r], xv, w1);
                ffma2(ag[r], xv, w2);
                ffma2(ao[r], xv, w3);
            }
        }

        // z += h @ U  (H=128 inner dim)
        #pragma unroll 4
        for (int j = 0; j < HCELLS; j++) {
            const ull u0 = *(const ull*)&Up[j * G4];
            const ull u1 = *(const ull*)&Up[j * G4 + 128];
            const ull u2 = *(const ull*)&Up[j * G4 + 256];
            const ull u3 = *(const ull*)&Up[j * G4 + 384];
            #pragma unroll
            for (int r = 0; r < RP; r++) {
                const ull hv = *(const ull*)&hsh[cur][j][rbase + r];  // broadcast LDS.64
                ffma2(ai[r], hv, u0);
                ffma2(af[r], hv, u1);
                ffma2(ag[r], hv, u2);
                ffma2(ao[r], hv, u3);
            }
        }

        // gates + state update; write NEW h into the other buffer
        #pragma unroll
        for (int r = 0; r < RP; r++) {
            #pragma unroll
            for (int s = 0; s < 2; s++) {     // s=0 -> unit 2kp, s=1 -> unit 2kp+1
                const float zi = s ? hi32(ai[r]) : lo32(ai[r]);
                const float zf = s ? hi32(af[r]) : lo32(af[r]);
                const float zg = s ? hi32(ag[r]) : lo32(ag[r]);
                const float zo = s ? hi32(ao[r]) : lo32(ao[r]);
                const float ig = sigm(zi);
                const float fg = sigm(zf);
                const float gg = fmaxf(zg, 0.0f);             // relu candidate
                const float og = sigm(zo);
                const float cn = fmaf(fg, c[r][s], ig * gg);
                c[r][s] = cn;
                const float hn = og * fmaxf(cn, 0.0f);        // relu cell activation
                hsh[nxt][2 * kp + s][rbase + r] = make_float2(hn, hn);
            }
        }

        // commit prefetched x for next timestep into the other buffer
        if (t < TSTEPS - 1) {
            xsh[nxt][f0][r0] = make_float2(xp0, xp0);
            if (xrow1) xsh[nxt][f1][r1] = make_float2(xp1, xp1);
        }

        __syncthreads();   // single barrier per step: publish h/x for next step
    }

    // epilogue: logits = h @ Wd + bd, softmax (tiny; one thread per row).
    // Final h is in buffer TSTEPS&1 == 0.
    if (tid < RTILE) {
        const int fb = TSTEPS & 1;
        const int r = tid;
        float logit[NCLS];
        #pragma unroll
        for (int d = 0; d < NCLS; d++) logit[d] = bd[d];
        for (int kk = 0; kk < HCELLS; kk++) {
            const float hv = hsh[fb][kk][r].x;
            #pragma unroll
            for (int d = 0; d < NCLS; d++)
                logit[d] = fmaf(hv, Wd[kk * NCLS + d], logit[d]);
        }
        float m = logit[0];
        #pragma unroll
        for (int d = 1; d < NCLS; d++) m = fmaxf(m, logit[d]);
        float s = 0.0f;
        #pragma unroll
        for (int d = 0; d < NCLS; d++) { logit[d] = __expf(logit[d] - m); s += logit[d]; }
        const float inv = 1.0f / s;
        #pragma unroll
        for (int d = 0; d < NCLS; d++) out[(row0 + r) * NCLS + d] = logit[d] * inv;
    }
}

extern "C" void kernel_launch(void* const* d_in, const int* in_sizes, int n_in,
                              void* d_out, int out_size) {
    const float* x  = (const float*)d_in[0];
    const float* W  = (const float*)d_in[1];
    const float* U  = (const float*)d_in[2];
    const float* b  = (const float*)d_in[3];
    const float* Wd = (const float*)d_in[4];
    const float* bd = (const float*)d_in[5];
    float* out = (float*)d_out;

    const int B = in_sizes[0] / (TSTEPS * FDIM);   // 16384
    lstm_fused<<<B / RTILE, 256>>>(x, W, U, b, Wd, bd, out);
}